// round 4
// baseline (speedup 1.0000x reference)
#include <cuda_runtime.h>
#include <cstdint>

// DiffKS: fused time-varying FIR (order 6) + time-varying all-pole IIR (order 2).
//   x[t]  = y[t] + sum_{k=1..6} Ae[b,t,k-1] * y[t-k]     (zero history)
//   out[t]= x[t] - sum_{k=1..2} Al[b,t,k-1] * out[t-k]   (zero initial state)
//
// Per-(batch,chunk) thread with IIR warmup (contractive: |a|<=0.25 -> ~0.64/step,
// WARM=36 -> ~1e-7 state error, below fp32 noise). Chunk 0 exact via t==0 reset.
//
// R3 lessons: (a) LDG->reg->STS staging = 200 regs + only 1 phase lookahead;
// (b) grid 336 @ 2 CTA/SM = 2x makespan. This version: cp.async (LDGSTS) 3-stage
// smem ring (2 phases lookahead, no reg landing), grid 288 = exact single wave,
// half-swap swizzle for conflict-free LDS.128 at pitch 18.

#define BATCH  48
#define TLEN   88200
#define CHUNK  116
#define WARM   36
#define G      8
#define PHASES ((CHUNK + WARM) / G)      // 19
#define CPB    128
#define NCH    761                       // ceil(TLEN/CHUNK)
#define BPR    6                         // 6*128=768 >= 761 ; grid = 288 = 2/SM single wave
#define STAGES 3
#define ITEMS  18                        // per chunk per phase: 2 y + 12 ae + 4 al (float4)
#define STAGE_F4 (CPB * ITEMS)           // 2304
#define SMEM_BYTES (STAGES * STAGE_F4 * 16)   // 110592

#define Y_MAX  (TLEN / 4 - 1)            // 22049
#define AE_MAX (TLEN * 3 / 2 - 1)        // 132299
#define AL_MAX (TLEN / 2 - 1)            // 44099

__device__ __forceinline__ void cp16(uint32_t dst_smem, const float4* src) {
    asm volatile("cp.async.ca.shared.global [%0], [%1], 16;"
                 :: "r"(dst_smem), "l"(src));
}
__device__ __forceinline__ void cp_commit() {
    asm volatile("cp.async.commit_group;");
}
__device__ __forceinline__ void cp_wait1() {
    asm volatile("cp.async.wait_group 1;");
}

__device__ __forceinline__ int clampi(int v, int hi) {
    return min(max(v, 0), hi);
}

// slot within a stage for (chunk w, item i): pitch 18, halves swapped for odd (w>>2)
__device__ __forceinline__ int slot_of(int w, int item) {
    int b = (w >> 2) & 1;
    int pos = item + 9 * b;
    if (pos >= 18) pos -= 18;
    return w * ITEMS + pos;
}

__global__ void __launch_bounds__(CPB, 2)
diffks_kernel(const float* __restrict__ y,
              const float* __restrict__ Ae,
              const float* __restrict__ Al,
              float* __restrict__ out)
{
    extern __shared__ float4 sm[];
    const int tid   = threadIdx.x;
    const int b     = blockIdx.x / BPR;
    const int seg   = blockIdx.x % BPR;
    const int cbase = seg * CPB;

    const float4* yg  = reinterpret_cast<const float4*>(y  + (size_t)b * TLEN);
    const float4* aeg = reinterpret_cast<const float4*>(Ae + (size_t)b * TLEN * 6);
    const float4* alg = reinterpret_cast<const float4*>(Al + (size_t)b * TLEN * 2);
    float*        ob  = out + (size_t)b * TLEN;

    const uint32_t smem_base = (uint32_t)__cvta_generic_to_shared(sm);

    // ---- loader descriptors: base f4 index at phase 0 + smem slot byte offset ----
    int yidx[2];  uint32_t ysl[2];
    int aeidx[12]; uint32_t aesl[12];
    int alidx[4]; uint32_t alsl[4];
    #pragma unroll
    for (int j = 0; j < 2; j++) {          // y: items 0,1 ; idx = (t>>2)+k, +2/phase
        int f = tid + CPB * j; int w = f >> 1; int k = f & 1;
        int t0 = (cbase + w) * CHUNK - WARM;       // mult of 4 (can be negative)
        yidx[j] = (t0 >> 2) + k;
        ysl[j]  = (uint32_t)(slot_of(w, 0 + k) * 16);
    }
    #pragma unroll
    for (int j = 0; j < 12; j++) {         // ae: items 2..13 ; idx = 3*(t>>1)+k, +12/phase
        int f = tid + CPB * j; int w = f / 12; int k = f - 12 * w;
        int t0 = (cbase + w) * CHUNK - WARM;
        aeidx[j] = 3 * (t0 >> 1) + k;
        aesl[j]  = (uint32_t)(slot_of(w, 2 + k) * 16);
    }
    #pragma unroll
    for (int j = 0; j < 4; j++) {          // al: items 14..17 ; idx = (t>>1)+k, +4/phase
        int f = tid + CPB * j; int w = f >> 2; int k = f & 3;
        int t0 = (cbase + w) * CHUNK - WARM;
        alidx[j] = (t0 >> 1) + k;
        alsl[j]  = (uint32_t)(slot_of(w, 14 + k) * 16);
    }

    // ---- issue one phase's block loads into stage slot s ----
    auto issue_phase = [&](int pf, int s) {
        uint32_t sb = smem_base + (uint32_t)(s * STAGE_F4 * 16);
        #pragma unroll
        for (int j = 0; j < 2; j++)
            cp16(sb + ysl[j],  yg  + clampi(yidx[j]  + 2 * pf,  Y_MAX));
        #pragma unroll
        for (int j = 0; j < 12; j++)
            cp16(sb + aesl[j], aeg + clampi(aeidx[j] + 12 * pf, AE_MAX));
        #pragma unroll
        for (int j = 0; j < 4; j++)
            cp16(sb + alsl[j], alg + clampi(alidx[j] + 4 * pf,  AL_MAX));
    };

    // ---- prologue: phases 0..STAGES-2 ----
    #pragma unroll
    for (int s = 0; s < STAGES - 1; s++) {
        issue_phase(s, s);
        cp_commit();
    }

    // ---- reader pointers (half-swap swizzle) ----
    const int rb   = (tid >> 2) & 1;
    const int base = tid * ITEMS;
    // low half = items 0..8, high half = items 9..17
    const int offL = base + 9 * rb;
    const int offH = base + 9 * (1 - rb);

    const int start = (cbase + tid) * CHUNK;
    int tg = start - WARM;                 // current phase start time

    float h0 = 0, h1 = 0, h2 = 0, h3 = 0, h4 = 0, h5 = 0;
    float s1 = 0, s2 = 0;

    for (int p = 0; p < PHASES; p++) {
        cp_wait1();
        __syncthreads();

        int pf = p + STAGES - 1;
        if (pf < PHASES) issue_phase(pf, pf % STAGES);
        cp_commit();

        const float4* L = sm + (p % STAGES) * STAGE_F4 + offL;
        const float4* H = sm + (p % STAGES) * STAGE_F4 + offH;

        #pragma unroll
        for (int g = 0; g < 2; g++) {
            float4 y4, e0, e1, e2, e3, e4, e5, l0, l1;
            if (g == 0) {
                y4 = L[0];
                e0 = L[2]; e1 = L[3]; e2 = L[4]; e3 = L[5]; e4 = L[6]; e5 = L[7];
                l0 = H[5]; l1 = H[6];
            } else {
                y4 = L[1];
                e0 = L[8]; e1 = H[0]; e2 = H[1]; e3 = H[2]; e4 = H[3]; e5 = H[4];
                l0 = H[7]; l1 = H[8];
            }

            int t = tg + 4 * g;
            if (t == 0) {                  // sequence start: exact zero state
                h0 = h1 = h2 = h3 = h4 = h5 = 0.f;
                s1 = s2 = 0.f;
            }

            float4 o4;
            float x, yo;

            // t+0 : Ae = e0.xyzw, e1.xy ; Al = l0.xy
            x  = y4.x + e0.x*h0 + e0.y*h1 + e0.z*h2 + e0.w*h3 + e1.x*h4 + e1.y*h5;
            yo = x - l0.x*s1 - l0.y*s2;
            s2 = s1; s1 = yo; o4.x = yo;
            h5 = h4; h4 = h3; h3 = h2; h2 = h1; h1 = h0; h0 = y4.x;

            // t+1 : Ae = e1.zw, e2.xyzw ; Al = l0.zw
            x  = y4.y + e1.z*h0 + e1.w*h1 + e2.x*h2 + e2.y*h3 + e2.z*h4 + e2.w*h5;
            yo = x - l0.z*s1 - l0.w*s2;
            s2 = s1; s1 = yo; o4.y = yo;
            h5 = h4; h4 = h3; h3 = h2; h2 = h1; h1 = h0; h0 = y4.y;

            // t+2 : Ae = e3.xyzw, e4.xy ; Al = l1.xy
            x  = y4.z + e3.x*h0 + e3.y*h1 + e3.z*h2 + e3.w*h3 + e4.x*h4 + e4.y*h5;
            yo = x - l1.x*s1 - l1.y*s2;
            s2 = s1; s1 = yo; o4.z = yo;
            h5 = h4; h4 = h3; h3 = h2; h2 = h1; h1 = h0; h0 = y4.z;

            // t+3 : Ae = e4.zw, e5.xyzw ; Al = l1.zw
            x  = y4.w + e4.z*h0 + e4.w*h1 + e5.x*h2 + e5.y*h3 + e5.z*h4 + e5.w*h5;
            yo = x - l1.z*s1 - l1.w*s2;
            s2 = s1; s1 = yo; o4.w = yo;
            h5 = h4; h4 = h3; h3 = h2; h2 = h1; h1 = h0; h0 = y4.w;

            if (t >= start && t < TLEN) {
                *reinterpret_cast<float4*>(ob + t) = o4;
            }
        }
        tg += G;
    }
}

extern "C" void kernel_launch(void* const* d_in, const int* in_sizes, int n_in,
                              void* d_out, int out_size)
{
    const float* y  = (const float*)d_in[0];
    const float* Ae = (const float*)d_in[1];
    const float* Al = (const float*)d_in[2];
    float* out = (float*)d_out;

    cudaFuncSetAttribute(diffks_kernel,
                         cudaFuncAttributeMaxDynamicSharedMemorySize, SMEM_BYTES);

    diffks_kernel<<<BATCH * BPR, CPB, SMEM_BYTES>>>(y, Ae, Al, out);
}

// round 5
// speedup vs baseline: 1.4929x; 1.4929x over previous
#include <cuda_runtime.h>

// DiffKS split pipeline:
//   Kernel A (FIR, sample-parallel, coalesced):  x[t] = y[t] + sum_k Ae[t,k]*y[t-1-k]
//   Kernel B (IIR, chunk-per-thread + warmup):   out[t] = x[t] - a1[t]*out[t-1] - a2[t]*out[t-2]
//
// R2 lesson: fused chunk-per-thread kernel is l1tex-wavefront-bound, dominated by
// uncoalesced Ae loads (6/9 of loads). FIR is fully parallel -> move Ae consumption
// into a coalesced sample-parallel kernel; IIR kernel keeps the proven R2 structure
// with only 12B/sample of loads. R3/R4 lesson: no block-lockstep pipelines.

#define BATCH 48
#define TLEN  88200

__device__ float g_x[BATCH * TLEN];     // intermediate x (16.9 MB scratch)

// ---------------- Kernel A: FIR (sample-parallel) ----------------
#define TPB_A 128
#define SPB   512                               // samples per block (4 per thread)
#define TBLK  ((TLEN + SPB - 1) / SPB)          // 173 tiles per row
#define AE_F4_ROW (TLEN * 3 / 2)                // 132300 float4 per row of Ae
#define Y_F4_ROW  (TLEN / 4)                    // 22050 float4 per row of y

__global__ void __launch_bounds__(TPB_A)
fir_kernel(const float* __restrict__ y, const float* __restrict__ Ae)
{
    __shared__ float4 sAe[TPB_A * 7];           // per-thread pitch 7 (odd -> conflict-free LDS.128)
    __shared__ float4 sY[132];                  // 2 halo f4 + 128 tile f4

    const int tid  = threadIdx.x;
    const int b    = blockIdx.x / TBLK;
    const int tile = blockIdx.x % TBLK;

    const float4* yg  = reinterpret_cast<const float4*>(y)  + (size_t)b * Y_F4_ROW;
    const float4* aeg = reinterpret_cast<const float4*>(Ae) + (size_t)b * AE_F4_ROW;

    // ---- stage Ae tile: 768 f4, flat coalesced; scatter to pitch-7 slots ----
    {
        const int base = tile * (SPB * 6 / 4);  // tile*768
        #pragma unroll
        for (int j = 0; j < 6; j++) {
            int f = tid + TPB_A * j;            // 0..767
            int gi = min(base + f, AE_F4_ROW - 1);
            int w = f / 6, k = f - 6 * w;
            sAe[w * 7 + k] = aeg[gi];
        }
    }
    // ---- stage y tile + 2-f4 front halo (zero before row start) ----
    {
        const int base = tile * (SPB / 4) - 2;  // local l -> global f4 base+l
        int l = tid;
        int gi = base + l;
        sY[l] = (gi < 0) ? make_float4(0.f, 0.f, 0.f, 0.f)
                         : yg[min(gi, Y_F4_ROW - 1)];
        if (tid < 4) {
            l = tid + TPB_A;
            if (l < 132) {
                gi = base + l;
                sY[l] = (gi < 0) ? make_float4(0.f, 0.f, 0.f, 0.f)
                                 : yg[min(gi, Y_F4_ROW - 1)];
            }
        }
    }
    __syncthreads();

    // ---- compute 4 samples ----
    const int T0 = tile * SPB + 4 * tid;
    if (T0 >= TLEN) return;

    float4 y4  = sY[2 + tid];
    float4 ym1 = sY[1 + tid];
    float4 ym2 = sY[tid];
    float h0 = ym1.w, h1 = ym1.z, h2 = ym1.y, h3 = ym1.x;
    float h4 = ym2.w, h5 = ym2.z;

    float4 e0 = sAe[tid * 7 + 0];
    float4 e1 = sAe[tid * 7 + 1];
    float4 e2 = sAe[tid * 7 + 2];
    float4 e3 = sAe[tid * 7 + 3];
    float4 e4 = sAe[tid * 7 + 4];
    float4 e5 = sAe[tid * 7 + 5];

    float4 x4;
    // sample T0+0 : Ae = e0.xyzw, e1.xy
    x4.x = y4.x + e0.x*h0 + e0.y*h1 + e0.z*h2 + e0.w*h3 + e1.x*h4 + e1.y*h5;
    h5 = h4; h4 = h3; h3 = h2; h2 = h1; h1 = h0; h0 = y4.x;
    // sample T0+1 : Ae = e1.zw, e2.xyzw
    x4.y = y4.y + e1.z*h0 + e1.w*h1 + e2.x*h2 + e2.y*h3 + e2.z*h4 + e2.w*h5;
    h5 = h4; h4 = h3; h3 = h2; h2 = h1; h1 = h0; h0 = y4.y;
    // sample T0+2 : Ae = e3.xyzw, e4.xy
    x4.z = y4.z + e3.x*h0 + e3.y*h1 + e3.z*h2 + e3.w*h3 + e4.x*h4 + e4.y*h5;
    h5 = h4; h4 = h3; h3 = h2; h2 = h1; h1 = h0; h0 = y4.z;
    // sample T0+3 : Ae = e4.zw, e5.xyzw
    x4.w = y4.w + e4.z*h0 + e4.w*h1 + e5.x*h2 + e5.y*h3 + e5.z*h4 + e5.w*h5;

    *reinterpret_cast<float4*>(g_x + (size_t)b * TLEN + T0) = x4;
}

// ---------------- Kernel B: IIR (chunk-per-thread + warmup) ----------------
#define CHUNK 112
#define WARM  32
#define NCH   ((TLEN + CHUNK - 1) / CHUNK)      // 788
#define NTH   (BATCH * NCH)                     // 37824
#define TPB_B 128

__global__ void __launch_bounds__(TPB_B)
iir_kernel(const float* __restrict__ Al, float* __restrict__ out)
{
    int gid = blockIdx.x * blockDim.x + threadIdx.x;
    if (gid >= NTH) return;

    int b = gid / NCH;
    int c = gid - b * NCH;

    int start  = c * CHUNK;
    int wstart = max(start - WARM, 0);
    int tend   = min(start + CHUNK, TLEN);

    const float4* xb4 = reinterpret_cast<const float4*>(g_x + (size_t)b * TLEN);
    const float4* al4 = reinterpret_cast<const float4*>(Al + (size_t)b * TLEN * 2);
    float*        ob  = out + (size_t)b * TLEN;

    float s1 = 0.f, s2 = 0.f;

    // prologue loads
    float4 x4 = xb4[wstart >> 2];
    float4 l0 = al4[wstart >> 1];
    float4 l1 = al4[(wstart >> 1) + 1];

    for (int t = wstart; t < tend; t += 4) {
        // prefetch next iteration (clamped; last iter re-reads current -> L1 hit)
        int tn = t + 4;
        if (tn >= tend) tn = t;
        float4 nx4 = xb4[tn >> 2];
        float4 nl0 = al4[tn >> 1];
        float4 nl1 = al4[(tn >> 1) + 1];

        float4 o4;
        float yo;
        // t+0 : a1 = l0.x, a2 = l0.y
        yo = x4.x - l0.x*s1 - l0.y*s2;  s2 = s1; s1 = yo; o4.x = yo;
        // t+1 : a1 = l0.z, a2 = l0.w
        yo = x4.y - l0.z*s1 - l0.w*s2;  s2 = s1; s1 = yo; o4.y = yo;
        // t+2 : a1 = l1.x, a2 = l1.y
        yo = x4.z - l1.x*s1 - l1.y*s2;  s2 = s1; s1 = yo; o4.z = yo;
        // t+3 : a1 = l1.z, a2 = l1.w
        yo = x4.w - l1.z*s1 - l1.w*s2;  s2 = s1; s1 = yo; o4.w = yo;

        if (t >= start) {
            *reinterpret_cast<float4*>(ob + t) = o4;
        }

        x4 = nx4; l0 = nl0; l1 = nl1;
    }
}

extern "C" void kernel_launch(void* const* d_in, const int* in_sizes, int n_in,
                              void* d_out, int out_size)
{
    const float* y  = (const float*)d_in[0];
    const float* Ae = (const float*)d_in[1];
    const float* Al = (const float*)d_in[2];
    float* out = (float*)d_out;

    fir_kernel<<<BATCH * TBLK, TPB_A>>>(y, Ae);
    iir_kernel<<<(NTH + TPB_B - 1) / TPB_B, TPB_B>>>(Al, out);
}